// round 16
// baseline (speedup 1.0000x reference)
#include <cuda_runtime.h>
#include <cuda_fp16.h>
#include <cstdint>

#define N_NODES  100000
#define N_EDGES  1600000
#define N_GRAPHS 2048
#define DIM      128
#define SCAN_B   1024
#define NSCAN    ((N_NODES + SCAN_B - 1) / SCAN_B)   // 98

// -------- scratch --------------------------------------------------------
__device__ __align__(256) __half g_hx  [N_NODES * DIM];   // fp16 x
__device__ __align__(256) __half g_agg [N_NODES * DIM];   // fp16 GIN aggregate
__device__ __align__(256) __half g_hh  [N_NODES * DIM];   // fp16 h (GIN out * dinv)
__device__ __align__(256) __half g_t   [N_NODES * DIM];   // fp16 GCN aggregate
__device__ __align__(256) __half g_wt  [3 * DIM * DIM];   // fp16 W^T [n][k] x3
__device__ __align__(256) float  g_dinv[N_NODES];
__device__ __align__(256) float  g_pool[N_GRAPHS * DIM];
__device__ __align__(256) int    g_cnt [N_NODES];
__device__ __align__(256) int    g_off [N_NODES];
__device__ __align__(256) int    g_cur [N_NODES];
__device__ __align__(256) int    g_bsum[NSCAN + 2];
__device__ __align__(256) int    g_csr [N_EDGES];

__device__ __forceinline__ uint32_t smem_u32(const void* p) {
    uint32_t a;
    asm("{ .reg .u64 t; cvta.to.shared.u64 t, %1; cvt.u32.u64 %0, t; }" : "=r"(a) : "l"(p));
    return a;
}
__device__ __forceinline__ void cp16(uint32_t dst, const void* src, uint32_t nbytes) {
    asm volatile("cp.async.cg.shared.global [%0], [%1], 16, %2;"
                 :: "r"(dst), "l"(src), "r"(nbytes) : "memory");
}

// ======== fp16 conversion of x (one-shot) ================================
__global__ void k_half(const float* __restrict__ x) {
    int i = blockIdx.x * blockDim.x + threadIdx.x;
    if (i >= N_NODES * (DIM / 4)) return;
    float4 v = ((const float4*)x)[i];
    __half2 a = __floats2half2_rn(v.x, v.y);
    __half2 b = __floats2half2_rn(v.z, v.w);
    uint2 o;
    o.x = *(uint32_t*)&a;
    o.y = *(uint32_t*)&b;
    ((uint2*)g_hx)[i] = o;
}

// ======== weight transpose + fp16 convert (one-shot) =====================
__global__ void k_wconv(const float* __restrict__ w1, const float* __restrict__ w2,
                        const float* __restrict__ w3) {
    int i = blockIdx.x * blockDim.x + threadIdx.x;
    if (i >= 3 * DIM * DIM) return;
    int z = i / (DIM * DIM);
    int r = i - z * DIM * DIM;
    int n = r / DIM, k = r - n * DIM;
    const float* src = (z == 0) ? w1 : (z == 1) ? w2 : w3;
    g_wt[i] = __float2half_rn(src[(size_t)k * DIM + n]);
}

// ======== CSR build ======================================================
__global__ void k_count(const int* __restrict__ ei, int E) {
    int e = blockIdx.x * blockDim.x + threadIdx.x;
    if (e >= E) return;
    atomicAdd(&g_cnt[ei[E + e]], 1);
}

__global__ void k_scanA() {
    __shared__ int ws[32];
    int tid = threadIdx.x;
    int lane = tid & 31, wrp = tid >> 5;
    int i = blockIdx.x * SCAN_B + tid;
    int v = (i < N_NODES) ? g_cnt[i] : 0;
    int xv = v;
#pragma unroll
    for (int o = 1; o < 32; o <<= 1) {
        int t = __shfl_up_sync(0xffffffffu, xv, o);
        if (lane >= o) xv += t;
    }
    if (lane == 31) ws[wrp] = xv;
    __syncthreads();
    if (wrp == 0) {
        int y = ws[lane];
#pragma unroll
        for (int o = 1; o < 32; o <<= 1) {
            int t = __shfl_up_sync(0xffffffffu, y, o);
            if (lane >= o) y += t;
        }
        ws[lane] = y;
    }
    __syncthreads();
    int incl = xv + ((wrp == 0) ? 0 : ws[wrp - 1]);
    if (i < N_NODES) g_off[i] = incl - v;
    if (tid == SCAN_B - 1) g_bsum[blockIdx.x] = incl;
}

__global__ void k_scanC() {
    __shared__ int sh[256];
    int tid = threadIdx.x;
    int v = (tid < NSCAN) ? g_bsum[tid] : 0;
    sh[tid] = v;
    __syncthreads();
#pragma unroll
    for (int o = 1; o < 256; o <<= 1) {
        int t = (tid >= o) ? sh[tid - o] : 0;
        __syncthreads();
        sh[tid] += t;
        __syncthreads();
    }
    int inc = sh[tid];
    __syncthreads();
    sh[tid] = inc - v;          // exclusive
    __syncthreads();
    int i = blockIdx.x * blockDim.x + tid;
    if (i >= N_NODES) return;
    int off = g_off[i] + sh[i / SCAN_B];
    g_off[i] = off;
    g_cur[i] = off;
    g_dinv[i] = rsqrtf((float)(g_cnt[i] + 1));
}

__global__ void k_fill(const int* __restrict__ ei, int E) {
    int e = blockIdx.x * blockDim.x + threadIdx.x;
    if (e >= E) return;
    int s = ei[e];
    int d = ei[E + e];
    int pos = atomicAdd(&g_cur[d], 1);
    g_csr[pos] = s;
}

// ======== pull aggregation over fp16, warp per node, fp16 output =========
template <int GCN>
__global__ void k_pull_h(const __half* __restrict__ feat, __half* __restrict__ out) {
    int w = (blockIdx.x * blockDim.x + threadIdx.x) >> 5;
    if (w >= N_NODES) return;
    int lane = threadIdx.x & 31;
    const uint2* fp = (const uint2*)feat;     // 4 halves per uint2, 32 per row
    int beg = g_off[w];
    int end = beg + g_cnt[w];
    uint2 sv = fp[(size_t)w * 32 + lane];
    float2 sa = __half22float2(*(__half2*)&sv.x);
    float2 sb = __half22float2(*(__half2*)&sv.y);
    float4 acc = make_float4(sa.x, sa.y, sb.x, sb.y);
    int i = beg;
    for (; i + 4 <= end; i += 4) {
        int s0 = g_csr[i], s1 = g_csr[i + 1], s2 = g_csr[i + 2], s3 = g_csr[i + 3];
        uint2 r0 = fp[(size_t)s0 * 32 + lane];
        uint2 r1 = fp[(size_t)s1 * 32 + lane];
        uint2 r2 = fp[(size_t)s2 * 32 + lane];
        uint2 r3 = fp[(size_t)s3 * 32 + lane];
#pragma unroll
        for (int q = 0; q < 4; q++) {
            uint2 rr = (q == 0) ? r0 : (q == 1) ? r1 : (q == 2) ? r2 : r3;
            float2 fa = __half22float2(*(__half2*)&rr.x);
            float2 fb = __half22float2(*(__half2*)&rr.y);
            acc.x += fa.x; acc.y += fa.y; acc.z += fb.x; acc.w += fb.y;
        }
    }
    for (; i < end; i++) {
        uint2 rr = fp[(size_t)g_csr[i] * 32 + lane];
        float2 fa = __half22float2(*(__half2*)&rr.x);
        float2 fb = __half22float2(*(__half2*)&rr.y);
        acc.x += fa.x; acc.y += fa.y; acc.z += fb.x; acc.w += fb.y;
    }
    if (GCN) {
        float di = g_dinv[w];
        acc.x *= di; acc.y *= di; acc.z *= di; acc.w *= di;
    }
    __half2 oa = __floats2half2_rn(acc.x, acc.y);
    __half2 ob = __floats2half2_rn(acc.z, acc.w);
    uint2 o;
    o.x = *(uint32_t*)&oa;
    o.y = *(uint32_t*)&ob;
    ((uint2*)(out + (size_t)w * DIM))[lane] = o;
}

// ======== fp16 GEMM geometry (fully-resident A and B) ====================
// A: fp16 [128 m][128 k], row = 256B = 16 chunks of 16B, swizzle ch^(r&7).
// B: whole WT [128 n][128 k] fp16, row = 256B data + 16B pad = 272B stride
//    (68 uint32). Banks: (68n + idx) mod 32 = (4n + idx) mod 32 — for the
//    fragment pattern n=8 distinct, c=0..3 → all 32 banks distinct.
#define AH_BYTES 32768
#define BW_ROW_U32 68
#define BW_BYTES (128 * BW_ROW_U32 * 4)   // 34816
#define POOL_SMEM (AH_BYTES + BW_BYTES)           // 67584
#define GIN_SMEM  (AH_BYTES + 2 * BW_BYTES)       // 102400

#define MMA16(accq, aq, b0, b1) \
    asm volatile("mma.sync.aligned.m16n8k16.row.col.f32.f16.f16.f32 "       \
        "{%0,%1,%2,%3}, {%4,%5,%6,%7}, {%8,%9}, {%0,%1,%2,%3};"             \
        : "+f"((accq)[0]), "+f"((accq)[1]), "+f"((accq)[2]), "+f"((accq)[3])\
        : "r"((aq)[0]), "r"((aq)[1]), "r"((aq)[2]), "r"((aq)[3]),           \
          "r"(b0), "r"(b1))

// stage whole fp16 A tile (128 rows x 256B) from global row-major
#define STAGE_A_FULL(Xh, Nv) do {                                           \
    _Pragma("unroll")                                                       \
    for (int j = 0; j < 8; j++) {                                           \
        int idx = tid * 8 + j;               /* 0..2047 */                  \
        int r = idx >> 4, ch = idx & 15;                                    \
        int gm = m0 + r;                                                    \
        uint32_t d = smb + r * 256 + ((ch ^ (r & 7)) << 4);                 \
        cp16(d, (Xh) + (size_t)gm * DIM + ch * 8, (gm < (Nv)) ? 16u : 0u);  \
    }                                                                       \
} while (0)

// stage whole WT (128 n x 128 k fp16) at smem offset boff
#define STAGE_B_WHOLE(WT, boff) do {                                        \
    uint32_t b_dst = smb + (boff);                                          \
    _Pragma("unroll")                                                       \
    for (int j = 0; j < 8; j++) {                                           \
        int idx = tid * 8 + j;               /* 0..2047 */                  \
        int n = idx >> 4, ch = idx & 15;                                    \
        cp16(b_dst + n * (BW_ROW_U32 * 4) + ch * 16,                        \
             (WT) + (size_t)n * DIM + ch * 8, 16u);                         \
    }                                                                       \
} while (0)

// A fragments: 4 m16 tiles for k16-step `st`
#define LOAD_A_FRAGS(a) do {                                                \
    _Pragma("unroll")                                                       \
    for (int mi = 0; mi < 4; mi++) {                                        \
        int r = wm * 64 + mi * 16 + lrow + (sub & 1) * 8;                   \
        int ch = st * 2 + (sub >> 1);                                       \
        uint32_t addr = smb + r * 256 + ((ch ^ (r & 7)) << 4);              \
        asm volatile(                                                       \
            "ldmatrix.sync.aligned.m8n8.x4.shared.b16 {%0,%1,%2,%3}, [%4];" \
            : "=r"((a)[mi][0]), "=r"((a)[mi][1]), "=r"((a)[mi][2]),         \
              "=r"((a)[mi][3]) : "r"(addr));                                \
    }                                                                       \
} while (0)

// B fragments from whole-W region (uint32* Bp): k16-step `st`
#define LOAD_B_FRAGS(b, Bp) do {                                            \
    _Pragma("unroll")                                                       \
    for (int ni = 0; ni < 4; ni++) {                                        \
        int n = wn * 32 + ni * 8 + g;                                       \
        (b)[ni][0] = (Bp)[n * BW_ROW_U32 + st * 8 + c];                     \
        (b)[ni][1] = (Bp)[n * BW_ROW_U32 + st * 8 + c + 4];                 \
    }                                                                       \
} while (0)

// ======== fused GIN MLP (fp16): hh = half(dinv*relu(relu(A@W1+b1)@W2+b2)) =
__global__ __launch_bounds__(256, 2)
void k_gin_mlp(const __half* __restrict__ Xh, const __half* __restrict__ W1T,
               const float* __restrict__ b1v, const __half* __restrict__ W2T,
               const float* __restrict__ b2v, __half* __restrict__ HH, int N) {
    extern __shared__ char sm[];
    const uint32_t smb = smem_u32(sm);
    const int tid  = threadIdx.x;
    const int lane = tid & 31;
    const int wid  = tid >> 5;
    const int wm   = wid & 1;
    const int wn   = wid >> 1;
    const int g    = lane >> 2;
    const int c    = lane & 3;
    const int m0   = blockIdx.x * 128;
    const int sub  = lane >> 3, lrow = lane & 7;

    // stage A + whole W1 (group 0), whole W2 (group 1)
    STAGE_A_FULL(Xh, N);
    STAGE_B_WHOLE(W1T, AH_BYTES);
    asm volatile("cp.async.commit_group;" ::: "memory");
    STAGE_B_WHOLE(W2T, AH_BYTES + BW_BYTES);
    asm volatile("cp.async.commit_group;" ::: "memory");

    float acc[4][4][4];
#pragma unroll
    for (int mi = 0; mi < 4; mi++)
#pragma unroll
        for (int ni = 0; ni < 4; ni++)
#pragma unroll
            for (int q = 0; q < 4; q++) acc[mi][ni][q] = 0.f;

    asm volatile("cp.async.wait_group 1;" ::: "memory");   // A + W1 ready
    __syncthreads();

    // ======== phase 1: A @ W1 — 8 k16-steps, no barriers ========
    {
        const uint32_t* Bp = (const uint32_t*)(sm + AH_BYTES);
#pragma unroll
        for (int st = 0; st < 8; st++) {
            uint32_t a[4][4];
            LOAD_A_FRAGS(a);
            uint32_t b[4][2];
            LOAD_B_FRAGS(b, Bp);
#pragma unroll
            for (int mi = 0; mi < 4; mi++)
#pragma unroll
                for (int ni = 0; ni < 4; ni++)
                    MMA16(acc[mi][ni], a[mi], b[ni][0], b[ni][1]);
        }
    }
    __syncthreads();   // all phase-1 A reads done before overwrite

    // ---- t = half(relu(acc+b1)) overwrites A tile (same swizzled layout) --
#pragma unroll
    for (int ni = 0; ni < 4; ni++) {
        int col = wn * 32 + ni * 8 + 2 * c;
        float bb0 = b1v[col], bb1 = b1v[col + 1];
        int ch = wn * 4 + ni;            // 16B chunk containing col
        int bo = (col & 7) * 2;          // byte offset within chunk
#pragma unroll
        for (int mi = 0; mi < 4; mi++) {
            int r0 = wm * 64 + mi * 16 + g;
            int r1 = r0 + 8;
            __half2 v0 = __floats2half2_rn(fmaxf(acc[mi][ni][0] + bb0, 0.f),
                                           fmaxf(acc[mi][ni][1] + bb1, 0.f));
            __half2 v1 = __floats2half2_rn(fmaxf(acc[mi][ni][2] + bb0, 0.f),
                                           fmaxf(acc[mi][ni][3] + bb1, 0.f));
            *(__half2*)(sm + r0 * 256 + ((ch ^ (r0 & 7)) << 4) + bo) = v0;
            *(__half2*)(sm + r1 * 256 + ((ch ^ (r1 & 7)) << 4) + bo) = v1;
            acc[mi][ni][0] = acc[mi][ni][1] = acc[mi][ni][2] = acc[mi][ni][3] = 0.f;
        }
    }
    asm volatile("cp.async.wait_group 0;" ::: "memory");   // W2 ready
    __syncthreads();

    // ======== phase 2: t @ W2 — 8 k16-steps, no barriers ========
    {
        const uint32_t* Bp = (const uint32_t*)(sm + AH_BYTES + BW_BYTES);
#pragma unroll
        for (int st = 0; st < 8; st++) {
            uint32_t a[4][4];
            LOAD_A_FRAGS(a);
            uint32_t b[4][2];
            LOAD_B_FRAGS(b, Bp);
#pragma unroll
            for (int mi = 0; mi < 4; mi++)
#pragma unroll
                for (int ni = 0; ni < 4; ni++)
                    MMA16(acc[mi][ni], a[mi], b[ni][0], b[ni][1]);
        }
    }

    // ---- epilogue: hh = half(dinv * relu(acc + b2)) ----
#pragma unroll
    for (int ni = 0; ni < 4; ni++) {
        int col = wn * 32 + ni * 8 + 2 * c;
        float bb0 = b2v[col], bb1 = b2v[col + 1];
#pragma unroll
        for (int mi = 0; mi < 4; mi++) {
            int r0 = m0 + wm * 64 + mi * 16 + g;
            int r1 = r0 + 8;
            if (r0 < N) {
                float sc = g_dinv[r0];
                *(__half2*)(HH + (size_t)r0 * DIM + col) =
                    __floats2half2_rn(sc * fmaxf(acc[mi][ni][0] + bb0, 0.f),
                                      sc * fmaxf(acc[mi][ni][1] + bb1, 0.f));
            }
            if (r1 < N) {
                float sc = g_dinv[r1];
                *(__half2*)(HH + (size_t)r1 * DIM + col) =
                    __floats2half2_rn(sc * fmaxf(acc[mi][ni][2] + bb0, 0.f),
                                      sc * fmaxf(acc[mi][ni][3] + bb1, 0.f));
            }
        }
    }
}

// ======== GCN GEMM (fp16) with fused pooling =============================
__global__ __launch_bounds__(256, 2)
void k_gemm_pool(const __half* __restrict__ Xh, const __half* __restrict__ WT,
                 const float* __restrict__ bias,
                 const int* __restrict__ batch, float* __restrict__ pool, int N) {
    extern __shared__ char sm[];
    const uint32_t smb = smem_u32(sm);
    const int tid  = threadIdx.x;
    const int lane = tid & 31;
    const int wid  = tid >> 5;
    const int wm   = wid & 1;
    const int wn   = wid >> 1;
    const int g    = lane >> 2;
    const int c    = lane & 3;
    const int m0   = blockIdx.x * 128;
    const int sub  = lane >> 3, lrow = lane & 7;

    STAGE_A_FULL(Xh, N);
    STAGE_B_WHOLE(WT, AH_BYTES);
    asm volatile("cp.async.commit_group;" ::: "memory");

    float acc[4][4][4];
#pragma unroll
    for (int mi = 0; mi < 4; mi++)
#pragma unroll
        for (int ni = 0; ni < 4; ni++)
#pragma unroll
            for (int q = 0; q < 4; q++) acc[mi][ni][q] = 0.f;

    asm volatile("cp.async.wait_group 0;" ::: "memory");
    __syncthreads();

    {
        const uint32_t* Bp = (const uint32_t*)(sm + AH_BYTES);
#pragma unroll
        for (int st = 0; st < 8; st++) {
            uint32_t a[4][4];
            LOAD_A_FRAGS(a);
            uint32_t b[4][2];
            LOAD_B_FRAGS(b, Bp);
#pragma unroll
            for (int mi = 0; mi < 4; mi++)
#pragma unroll
                for (int ni = 0; ni < 4; ni++)
                    MMA16(acc[mi][ni], a[mi], b[ni][0], b[ni][1]);
        }
    }

    // ---- epilogue: pool[batch[m]] += relu(acc + b) ----
#pragma unroll
    for (int ni = 0; ni < 4; ni++) {
        int col = wn * 32 + ni * 8 + 2 * c;
        float bb0 = bias[col], bb1 = bias[col + 1];
#pragma unroll
        for (int mi = 0; mi < 4; mi++) {
            int r0 = m0 + wm * 64 + mi * 16 + g;
            int r1 = r0 + 8;
            if (r0 < N) {
                float* pp = pool + (size_t)batch[r0] * DIM + col;
                asm volatile("red.global.add.v2.f32 [%0], {%1,%2};"
                             :: "l"(pp), "f"(fmaxf(acc[mi][ni][0] + bb0, 0.f)),
                                "f"(fmaxf(acc[mi][ni][1] + bb1, 0.f)) : "memory");
            }
            if (r1 < N) {
                float* pp = pool + (size_t)batch[r1] * DIM + col;
                asm volatile("red.global.add.v2.f32 [%0], {%1,%2};"
                             :: "l"(pp), "f"(fmaxf(acc[mi][ni][2] + bb0, 0.f)),
                                "f"(fmaxf(acc[mi][ni][3] + bb1, 0.f)) : "memory");
            }
        }
    }
}

// ======== head ===========================================================
__global__ void k_head(const float* __restrict__ w1, const float* __restrict__ b1,
                       const float* __restrict__ w2, const float* __restrict__ b2,
                       float* __restrict__ out) {
    __shared__ float gs[128];
    __shared__ float ts[128];
    int g = blockIdx.x;
    int j = threadIdx.x;
    gs[j] = g_pool[(size_t)g * 128 + j];
    __syncthreads();
    float acc = b1[j];
#pragma unroll 8
    for (int k = 0; k < 128; k++) acc = fmaf(gs[k], w1[(size_t)k * 128 + j], acc);
    ts[j] = fmaxf(acc, 0.f);
    __syncthreads();
    if (j < 32) {
        float o0 = 0.f, o1 = 0.f, o2 = 0.f;
#pragma unroll
        for (int k = j; k < 128; k += 32) {
            float tv = ts[k];
            o0 = fmaf(tv, w2[k * 3 + 0], o0);
            o1 = fmaf(tv, w2[k * 3 + 1], o1);
            o2 = fmaf(tv, w2[k * 3 + 2], o2);
        }
#pragma unroll
        for (int off = 16; off; off >>= 1) {
            o0 += __shfl_down_sync(0xffffffffu, o0, off);
            o1 += __shfl_down_sync(0xffffffffu, o1, off);
            o2 += __shfl_down_sync(0xffffffffu, o2, off);
        }
        if (j == 0) {
            out[g * 3 + 0] = o0 + b2[0];
            out[g * 3 + 1] = o1 + b2[1];
            out[g * 3 + 2] = o2 + b2[2];
        }
    }
}

// ======== launcher =======================================================
extern "C" void kernel_launch(void* const* d_in, const int* in_sizes, int n_in,
                              void* d_out, int out_size) {
    const float* x      = (const float*)d_in[0];
    const int*   ei     = (const int*)d_in[1];
    const int*   batch  = (const int*)d_in[2];
    const float* gin_w1 = (const float*)d_in[3];
    const float* gin_b1 = (const float*)d_in[4];
    const float* gin_w2 = (const float*)d_in[5];
    const float* gin_b2 = (const float*)d_in[6];
    const float* gcn_w  = (const float*)d_in[7];
    const float* gcn_b  = (const float*)d_in[8];
    const float* lin1_w = (const float*)d_in[9];
    const float* lin1_b = (const float*)d_in[10];
    const float* lin2_w = (const float*)d_in[11];
    const float* lin2_b = (const float*)d_in[12];
    float*       out    = (float*)d_out;

    const int N = in_sizes[0] / DIM;       // 100000
    const int E = in_sizes[1] / 2;         // 1600000

    __half* hx_p;   cudaGetSymbolAddress((void**)&hx_p,   g_hx);
    __half* agg_p;  cudaGetSymbolAddress((void**)&agg_p,  g_agg);
    __half* hh_p;   cudaGetSymbolAddress((void**)&hh_p,   g_hh);
    __half* t_p;    cudaGetSymbolAddress((void**)&t_p,    g_t);
    __half* wt_p;   cudaGetSymbolAddress((void**)&wt_p,   g_wt);
    float*  pool_p; cudaGetSymbolAddress((void**)&pool_p, g_pool);
    int*    cnt_p;  cudaGetSymbolAddress((void**)&cnt_p,  g_cnt);

    static bool attr_done = false;
    if (!attr_done) {
        cudaFuncSetAttribute(k_gin_mlp,   cudaFuncAttributeMaxDynamicSharedMemorySize, GIN_SMEM);
        cudaFuncSetAttribute(k_gemm_pool, cudaFuncAttributeMaxDynamicSharedMemorySize, POOL_SMEM);
        attr_done = true;
    }

    const int TB = 256;

    // CSR build + one-shot conversions
    cudaMemsetAsync(cnt_p, 0, N_NODES * sizeof(int));
    k_count<<<(E + TB - 1) / TB, TB>>>(ei, E);
    k_half<<<(N_NODES * (DIM / 4) + TB - 1) / TB, TB>>>(x);
    k_wconv<<<(3 * DIM * DIM + TB - 1) / TB, TB>>>(gin_w1, gin_w2, gcn_w);
    k_scanA<<<NSCAN, SCAN_B>>>();
    k_scanC<<<(N + TB - 1) / TB, TB>>>();
    k_fill<<<(E + TB - 1) / TB, TB>>>(ei, E);

    int pblocks = (N * 32 + TB - 1) / TB;
    // GIN aggregate (pull over fp16 x): agg = half(x + sum x[src])
    k_pull_h<0><<<pblocks, TB>>>(hx_p, agg_p);

    int gblocks = (N + 127) / 128;          // 782
    // hh = half(dinv * relu(relu(agg@W1+b1)@W2+b2))
    k_gin_mlp<<<gblocks, 256, GIN_SMEM>>>(agg_p, wt_p + 0 * DIM * DIM, gin_b1,
                                          wt_p + 1 * DIM * DIM, gin_b2, hh_p, N);

    cudaMemsetAsync(pool_p, 0, N_GRAPHS * DIM * sizeof(float));

    // GCN aggregate (pull over fp16 h): t = half(dinv * (h + sum h[src]))
    k_pull_h<1><<<pblocks, TB>>>(hh_p, t_p);

    // pool[batch] += relu(t @ gcn_w + gcn_b)
    k_gemm_pool<<<gblocks, 256, POOL_SMEM>>>(t_p, wt_p + 2 * DIM * DIM, gcn_b,
                                             batch, pool_p, N);

    k_head<<<N_GRAPHS, 128>>>(lin1_w, lin1_b, lin2_w, lin2_b, out);
}

// round 17
// speedup vs baseline: 1.0633x; 1.0633x over previous
#include <cuda_runtime.h>
#include <cuda_fp16.h>
#include <cstdint>

#define N_NODES  100000
#define N_EDGES  1600000
#define N_GRAPHS 2048
#define DIM      128
#define SCAN_B   1024
#define NSCAN    ((N_NODES + SCAN_B - 1) / SCAN_B)   // 98

// -------- scratch --------------------------------------------------------
__device__ __align__(256) __half g_hx  [N_NODES * DIM];   // fp16 x
__device__ __align__(256) __half g_agg [N_NODES * DIM];   // fp16 GIN aggregate
__device__ __align__(256) __half g_hh  [N_NODES * DIM];   // fp16 h (GIN out * dinv)
__device__ __align__(256) __half g_t   [N_NODES * DIM];   // fp16 GCN aggregate
__device__ __align__(256) __half g_wt  [3 * DIM * DIM];   // fp16 W^T [n][k] x3
__device__ __align__(256) float  g_dinv[N_NODES];
__device__ __align__(256) float  g_pool[N_GRAPHS * DIM];
__device__ __align__(256) int    g_cnt [N_NODES];
__device__ __align__(256) int    g_off [N_NODES];
__device__ __align__(256) int    g_pos [N_EDGES];
__device__ __align__(256) int    g_bsum[NSCAN + 2];
__device__ __align__(256) int    g_csr [N_EDGES];

__device__ __forceinline__ uint32_t smem_u32(const void* p) {
    uint32_t a;
    asm("{ .reg .u64 t; cvta.to.shared.u64 t, %1; cvt.u32.u64 %0, t; }" : "=r"(a) : "l"(p));
    return a;
}
__device__ __forceinline__ void cp16(uint32_t dst, const void* src, uint32_t nbytes) {
    asm volatile("cp.async.cg.shared.global [%0], [%1], 16, %2;"
                 :: "r"(dst), "l"(src), "r"(nbytes) : "memory");
}

// ======== fp16 conversion of x (one-shot) ================================
__global__ void k_half(const float* __restrict__ x) {
    int i = blockIdx.x * blockDim.x + threadIdx.x;
    if (i >= N_NODES * (DIM / 4)) return;
    float4 v = ((const float4*)x)[i];
    __half2 a = __floats2half2_rn(v.x, v.y);
    __half2 b = __floats2half2_rn(v.z, v.w);
    uint2 o;
    o.x = *(uint32_t*)&a;
    o.y = *(uint32_t*)&b;
    ((uint2*)g_hx)[i] = o;
}

// ======== weight transpose + fp16 convert (one-shot) =====================
__global__ void k_wconv(const float* __restrict__ w1, const float* __restrict__ w2,
                        const float* __restrict__ w3) {
    int i = blockIdx.x * blockDim.x + threadIdx.x;
    if (i >= 3 * DIM * DIM) return;
    int z = i / (DIM * DIM);
    int r = i - z * DIM * DIM;
    int n = r / DIM, k = r - n * DIM;
    const float* src = (z == 0) ? w1 : (z == 1) ? w2 : w3;
    g_wt[i] = __float2half_rn(src[(size_t)k * DIM + n]);
}

// ======== CSR build ======================================================
// count: pos[e] = slot of edge e within its destination bucket
__global__ void k_count(const int* __restrict__ ei, int E) {
    int e = blockIdx.x * blockDim.x + threadIdx.x;
    if (e >= E) return;
    g_pos[e] = atomicAdd(&g_cnt[ei[E + e]], 1);
}

__global__ void k_scanA() {
    __shared__ int ws[32];
    int tid = threadIdx.x;
    int lane = tid & 31, wrp = tid >> 5;
    int i = blockIdx.x * SCAN_B + tid;
    int v = (i < N_NODES) ? g_cnt[i] : 0;
    int xv = v;
#pragma unroll
    for (int o = 1; o < 32; o <<= 1) {
        int t = __shfl_up_sync(0xffffffffu, xv, o);
        if (lane >= o) xv += t;
    }
    if (lane == 31) ws[wrp] = xv;
    __syncthreads();
    if (wrp == 0) {
        int y = ws[lane];
#pragma unroll
        for (int o = 1; o < 32; o <<= 1) {
            int t = __shfl_up_sync(0xffffffffu, y, o);
            if (lane >= o) y += t;
        }
        ws[lane] = y;
    }
    __syncthreads();
    int incl = xv + ((wrp == 0) ? 0 : ws[wrp - 1]);
    if (i < N_NODES) g_off[i] = incl - v;
    if (tid == SCAN_B - 1) g_bsum[blockIdx.x] = incl;
}

__global__ void k_scanC() {
    __shared__ int sh[256];
    int tid = threadIdx.x;
    int v = (tid < NSCAN) ? g_bsum[tid] : 0;
    sh[tid] = v;
    __syncthreads();
#pragma unroll
    for (int o = 1; o < 256; o <<= 1) {
        int t = (tid >= o) ? sh[tid - o] : 0;
        __syncthreads();
        sh[tid] += t;
        __syncthreads();
    }
    int inc = sh[tid];
    __syncthreads();
    sh[tid] = inc - v;          // exclusive
    __syncthreads();
    int i = blockIdx.x * blockDim.x + tid;
    if (i >= N_NODES) return;
    int off = g_off[i] + sh[i / SCAN_B];
    g_off[i] = off;
    g_dinv[i] = rsqrtf((float)(g_cnt[i] + 1));
}

// fill: no atomics — slot was precomputed in k_count
__global__ void k_fill(const int* __restrict__ ei, int E) {
    int e = blockIdx.x * blockDim.x + threadIdx.x;
    if (e >= E) return;
    int d = ei[E + e];
    g_csr[g_off[d] + g_pos[e]] = ei[e];
}

// ======== pull aggregation over fp16, warp per node, fp16 output =========
template <int GCN>
__global__ void k_pull_h(const __half* __restrict__ feat, __half* __restrict__ out) {
    int w = (blockIdx.x * blockDim.x + threadIdx.x) >> 5;
    if (w >= N_NODES) return;
    int lane = threadIdx.x & 31;
    const uint2* fp = (const uint2*)feat;     // 4 halves per uint2, 32 per row
    int beg = g_off[w];
    int end = beg + g_cnt[w];
    uint2 sv = fp[(size_t)w * 32 + lane];
    float2 sa = __half22float2(*(__half2*)&sv.x);
    float2 sb = __half22float2(*(__half2*)&sv.y);
    float4 acc = make_float4(sa.x, sa.y, sb.x, sb.y);
    int i = beg;
    for (; i + 4 <= end; i += 4) {
        int s0 = g_csr[i], s1 = g_csr[i + 1], s2 = g_csr[i + 2], s3 = g_csr[i + 3];
        uint2 r0 = fp[(size_t)s0 * 32 + lane];
        uint2 r1 = fp[(size_t)s1 * 32 + lane];
        uint2 r2 = fp[(size_t)s2 * 32 + lane];
        uint2 r3 = fp[(size_t)s3 * 32 + lane];
#pragma unroll
        for (int q = 0; q < 4; q++) {
            uint2 rr = (q == 0) ? r0 : (q == 1) ? r1 : (q == 2) ? r2 : r3;
            float2 fa = __half22float2(*(__half2*)&rr.x);
            float2 fb = __half22float2(*(__half2*)&rr.y);
            acc.x += fa.x; acc.y += fa.y; acc.z += fb.x; acc.w += fb.y;
        }
    }
    for (; i < end; i++) {
        uint2 rr = fp[(size_t)g_csr[i] * 32 + lane];
        float2 fa = __half22float2(*(__half2*)&rr.x);
        float2 fb = __half22float2(*(__half2*)&rr.y);
        acc.x += fa.x; acc.y += fa.y; acc.z += fb.x; acc.w += fb.y;
    }
    if (GCN) {
        float di = g_dinv[w];
        acc.x *= di; acc.y *= di; acc.z *= di; acc.w *= di;
    }
    __half2 oa = __floats2half2_rn(acc.x, acc.y);
    __half2 ob = __floats2half2_rn(acc.z, acc.w);
    uint2 o;
    o.x = *(uint32_t*)&oa;
    o.y = *(uint32_t*)&ob;
    ((uint2*)(out + (size_t)w * DIM))[lane] = o;
}

// ======== fp16 GEMM geometry (R15 proven config) =========================
// A: fp16 [128 m][128 k], row = 256B = 16 chunks of 16B, swizzle ch^(r&7).
// B: fp16 WT chunk [128 n][32 k], row padded to 80B (20 uint32).
#define AH_BYTES 32768
#define BH_ROW_U32 20
#define BH_BYTES (128 * BH_ROW_U32 * 4)   // 10240
#define HB0 AH_BYTES
#define HB1 (AH_BYTES + BH_BYTES)
#define HS_TOT (AH_BYTES + 2 * BH_BYTES)  // 53248

#define MMA16(accq, aq, b0, b1) \
    asm volatile("mma.sync.aligned.m16n8k16.row.col.f32.f16.f16.f32 "       \
        "{%0,%1,%2,%3}, {%4,%5,%6,%7}, {%8,%9}, {%0,%1,%2,%3};"             \
        : "+f"((accq)[0]), "+f"((accq)[1]), "+f"((accq)[2]), "+f"((accq)[3])\
        : "r"((aq)[0]), "r"((aq)[1]), "r"((aq)[2]), "r"((aq)[3]),           \
          "r"(b0), "r"(b1))

#define STAGE_A_FULL(Xh, Nv) do {                                           \
    _Pragma("unroll")                                                       \
    for (int j = 0; j < 8; j++) {                                           \
        int idx = tid * 8 + j;               /* 0..2047 */                  \
        int r = idx >> 4, ch = idx & 15;                                    \
        int gm = m0 + r;                                                    \
        uint32_t d = smb + r * 256 + ((ch ^ (r & 7)) << 4);                 \
        cp16(d, (Xh) + (size_t)gm * DIM + ch * 8, (gm < (Nv)) ? 16u : 0u);  \
    }                                                                       \
} while (0)

#define STAGE_BH(WT, buf, kb) do {                                          \
    uint32_t b_dst = smb + ((buf) ? HB1 : HB0);                             \
    _Pragma("unroll")                                                       \
    for (int j = 0; j < 2; j++) {                                           \
        int idx = tid * 2 + j;               /* 0..511 */                   \
        int n = idx >> 2, ch = idx & 3;                                     \
        cp16(b_dst + n * (BH_ROW_U32 * 4) + ch * 16,                        \
             (WT) + (size_t)n * DIM + (kb) + ch * 8, 16u);                  \
    }                                                                       \
    asm volatile("cp.async.commit_group;" ::: "memory");                    \
} while (0)

#define LOAD_A_FRAGS(a) do {                                                \
    _Pragma("unroll")                                                       \
    for (int mi = 0; mi < 4; mi++) {                                        \
        int r = wm * 64 + mi * 16 + lrow + (sub & 1) * 8;                   \
        int ch = st * 2 + (sub >> 1);                                       \
        uint32_t addr = smb + r * 256 + ((ch ^ (r & 7)) << 4);              \
        asm volatile(                                                       \
            "ldmatrix.sync.aligned.m8n8.x4.shared.b16 {%0,%1,%2,%3}, [%4];" \
            : "=r"((a)[mi][0]), "=r"((a)[mi][1]), "=r"((a)[mi][2]),         \
              "=r"((a)[mi][3]) : "r"(addr));                                \
    }                                                                       \
} while (0)

#define LOAD_B_FRAGS(b, Bp, ko) do {                                        \
    _Pragma("unroll")                                                       \
    for (int ni = 0; ni < 4; ni++) {                                        \
        int n = wn * 32 + ni * 8 + g;                                       \
        (b)[ni][0] = (Bp)[n * BH_ROW_U32 + (ko) + c];                       \
        (b)[ni][1] = (Bp)[n * BH_ROW_U32 + (ko) + c + 4];                   \
    }                                                                       \
} while (0)

// ======== fused GIN MLP (fp16): hh = half(dinv*relu(relu(A@W1+b1)@W2+b2)) =
__global__ __launch_bounds__(256, 2)
void k_gin_mlp(const __half* __restrict__ Xh, const __half* __restrict__ W1T,
               const float* __restrict__ b1v, const __half* __restrict__ W2T,
               const float* __restrict__ b2v, __half* __restrict__ HH, int N) {
    extern __shared__ char sm[];
    const uint32_t smb = smem_u32(sm);
    const int tid  = threadIdx.x;
    const int lane = tid & 31;
    const int wid  = tid >> 5;
    const int wm   = wid & 1;
    const int wn   = wid >> 1;
    const int g    = lane >> 2;
    const int c    = lane & 3;
    const int m0   = blockIdx.x * 128;
    const int sub  = lane >> 3, lrow = lane & 7;

    // stage A (whole) + W1 chunk 0
    STAGE_A_FULL(Xh, N);
    STAGE_BH(W1T, 0, 0);

    float acc[4][4][4];
#pragma unroll
    for (int mi = 0; mi < 4; mi++)
#pragma unroll
        for (int ni = 0; ni < 4; ni++)
#pragma unroll
            for (int q = 0; q < 4; q++) acc[mi][ni][q] = 0.f;

    // ======== phase 1: A @ W1 — 4 chunks of k32 (2 k16-steps each) ========
#pragma unroll
    for (int it = 0; it < 4; it++) {
        if (it < 3) {
            STAGE_BH(W1T, (it + 1) & 1, (it + 1) * 32);
            asm volatile("cp.async.wait_group 1;" ::: "memory");
        } else {
            asm volatile("cp.async.wait_group 0;" ::: "memory");
        }
        __syncthreads();
        const uint32_t* Bp = (const uint32_t*)(sm + ((it & 1) ? HB1 : HB0));
#pragma unroll
        for (int s2 = 0; s2 < 2; s2++) {
            const int st = it * 2 + s2;
            uint32_t a[4][4];
            LOAD_A_FRAGS(a);
            uint32_t b[4][2];
            LOAD_B_FRAGS(b, Bp, s2 * 8);
#pragma unroll
            for (int mi = 0; mi < 4; mi++)
#pragma unroll
                for (int ni = 0; ni < 4; ni++)
                    MMA16(acc[mi][ni], a[mi], b[ni][0], b[ni][1]);
        }
        __syncthreads();
    }

    // prefetch W2 chunk 0 while draining accumulators into the t tile
    STAGE_BH(W2T, 0, 0);

    // ---- t = half(relu(acc+b1)) overwrites A tile (same swizzled layout) --
#pragma unroll
    for (int ni = 0; ni < 4; ni++) {
        int col = wn * 32 + ni * 8 + 2 * c;
        float bb0 = b1v[col], bb1 = b1v[col + 1];
        int ch = wn * 4 + ni;            // chunk of 8 halves containing col
        int bo = (col & 7) * 2;          // byte offset within chunk
#pragma unroll
        for (int mi = 0; mi < 4; mi++) {
            int r0 = wm * 64 + mi * 16 + g;
            int r1 = r0 + 8;
            __half2 v0 = __floats2half2_rn(fmaxf(acc[mi][ni][0] + bb0, 0.f),
                                           fmaxf(acc[mi][ni][1] + bb1, 0.f));
            __half2 v1 = __floats2half2_rn(fmaxf(acc[mi][ni][2] + bb0, 0.f),
                                           fmaxf(acc[mi][ni][3] + bb1, 0.f));
            *(__half2*)(sm + r0 * 256 + ((ch ^ (r0 & 7)) << 4) + bo) = v0;
            *(__half2*)(sm + r1 * 256 + ((ch ^ (r1 & 7)) << 4) + bo) = v1;
            acc[mi][ni][0] = acc[mi][ni][1] = acc[mi][ni][2] = acc[mi][ni][3] = 0.f;
        }
    }
    __syncthreads();

    // ======== phase 2: t @ W2 ========
#pragma unroll
    for (int it = 0; it < 4; it++) {
        if (it < 3) {
            STAGE_BH(W2T, (it + 1) & 1, (it + 1) * 32);
            asm volatile("cp.async.wait_group 1;" ::: "memory");
        } else {
            asm volatile("cp.async.wait_group 0;" ::: "memory");
        }
        __syncthreads();
        const uint32_t* Bp = (const uint32_t*)(sm + ((it & 1) ? HB1 : HB0));
#pragma unroll
        for (int s2 = 0; s2 < 2; s2++) {
            const int st = it * 2 + s2;
            uint32_t a[4][4];
            LOAD_A_FRAGS(a);
            uint32_t b[4][2];
            LOAD_B_FRAGS(b, Bp, s2 * 8);
#pragma unroll
            for (int mi = 0; mi < 4; mi++)
#pragma unroll
                for (int ni = 0; ni < 4; ni++)
                    MMA16(acc[mi][ni], a[mi], b[ni][0], b[ni][1]);
        }
        __syncthreads();
    }

    // ---- epilogue: hh = half(dinv * relu(acc + b2)) ----
#pragma unroll
    for (int ni = 0; ni < 4; ni++) {
        int col = wn * 32 + ni * 8 + 2 * c;
        float bb0 = b2v[col], bb1 = b2v[col + 1];
#pragma unroll
        for (int mi = 0; mi < 4; mi++) {
            int r0 = m0 + wm * 64 + mi * 16 + g;
            int r1 = r0 + 8;
            if (r0 < N) {
                float sc = g_dinv[r0];
                *(__half2*)(HH + (size_t)r0 * DIM + col) =
                    __floats2half2_rn(sc * fmaxf(acc[mi][ni][0] + bb0, 0.f),
                                      sc * fmaxf(acc[mi][ni][1] + bb1, 0.f));
            }
            if (r1 < N) {
                float sc = g_dinv[r1];
                *(__half2*)(HH + (size_t)r1 * DIM + col) =
                    __floats2half2_rn(sc * fmaxf(acc[mi][ni][2] + bb0, 0.f),
                                      sc * fmaxf(acc[mi][ni][3] + bb1, 0.f));
            }
        }
    }
}

// ======== GCN GEMM (fp16) with fused pooling =============================
__global__ __launch_bounds__(256, 2)
void k_gemm_pool(const __half* __restrict__ Xh, const __half* __restrict__ WT,
                 const float* __restrict__ bias,
                 const int* __restrict__ batch, float* __restrict__ pool, int N) {
    extern __shared__ char sm[];
    const uint32_t smb = smem_u32(sm);
    const int tid  = threadIdx.x;
    const int lane = tid & 31;
    const int wid  = tid >> 5;
    const int wm   = wid & 1;
    const int wn   = wid >> 1;
    const int g    = lane >> 2;
    const int c    = lane & 3;
    const int m0   = blockIdx.x * 128;
    const int sub  = lane >> 3, lrow = lane & 7;

    STAGE_A_FULL(Xh, N);
    STAGE_BH(WT, 0, 0);

    float acc[4][4][4];
#pragma unroll
    for (int mi = 0; mi < 4; mi++)
#pragma unroll
        for (int ni = 0; ni < 4; ni++)
#pragma unroll
            for (int q = 0; q < 4; q++) acc[mi][ni][q] = 0.f;

#pragma unroll
    for (int it = 0; it < 4; it++) {
        if (it < 3) {
            STAGE_BH(WT, (it + 1) & 1, (it + 1) * 32);
            asm volatile("cp.async.wait_group 1;" ::: "memory");
        } else {
            asm volatile("cp.async.wait_group 0;" ::: "memory");
        }
        __syncthreads();
        const uint32_t* Bp = (const uint32_t*)(sm + ((it & 1) ? HB1 : HB0));
#pragma unroll
        for (int s2 = 0; s2 < 2; s2++) {
            const int st = it * 2 + s2;
            uint32_t a[4][4];
            LOAD_A_FRAGS(a);
            uint32_t b[4][2];
            LOAD_B_FRAGS(b, Bp, s2 * 8);
#pragma unroll
            for (int mi = 0; mi < 4; mi++)
#pragma unroll
                for (int ni = 0; ni < 4; ni++)
                    MMA16(acc[mi][ni], a[mi], b[ni][0], b[ni][1]);
        }
        __syncthreads();
    }

    // ---- epilogue: pool[batch[m]] += relu(acc + b) ----
#pragma unroll
    for (int ni = 0; ni < 4; ni++) {
        int col = wn * 32 + ni * 8 + 2 * c;
        float bb0 = bias[col], bb1 = bias[col + 1];
#pragma unroll
        for (int mi = 0; mi < 4; mi++) {
            int r0 = m0 + wm * 64 + mi * 16 + g;
            int r1 = r0 + 8;
            if (r0 < N) {
                float* pp = pool + (size_t)batch[r0] * DIM + col;
                asm volatile("red.global.add.v2.f32 [%0], {%1,%2};"
                             :: "l"(pp), "f"(fmaxf(acc[mi][ni][0] + bb0, 0.f)),
                                "f"(fmaxf(acc[mi][ni][1] + bb1, 0.f)) : "memory");
            }
            if (r1 < N) {
                float* pp = pool + (size_t)batch[r1] * DIM + col;
                asm volatile("red.global.add.v2.f32 [%0], {%1,%2};"
                             :: "l"(pp), "f"(fmaxf(acc[mi][ni][2] + bb0, 0.f)),
                                "f"(fmaxf(acc[mi][ni][3] + bb1, 0.f)) : "memory");
            }
        }
    }
}

// ======== head ===========================================================
__global__ void k_head(const float* __restrict__ w1, const float* __restrict__ b1,
                       const float* __restrict__ w2, const float* __restrict__ b2,
                       float* __restrict__ out) {
    __shared__ float gs[128];
    __shared__ float ts[128];
    int g = blockIdx.x;
    int j = threadIdx.x;
    gs[j] = g_pool[(size_t)g * 128 + j];
    __syncthreads();
    float acc = b1[j];
#pragma unroll 8
    for (int k = 0; k < 128; k++) acc = fmaf(gs[k], w1[(size_t)k * 128 + j], acc);
    ts[j] = fmaxf(acc, 0.f);
    __syncthreads();
    if (j < 32) {
        float o0 = 0.f, o1 = 0.f, o2 = 0.f;
#pragma unroll
        for (int k = j; k < 128; k += 32) {
            float tv = ts[k];
            o0 = fmaf(tv, w2[k * 3 + 0], o0);
            o1 = fmaf(tv, w2[k * 3 + 1], o1);
            o2 = fmaf(tv, w2[k * 3 + 2], o2);
        }
#pragma unroll
        for (int off = 16; off; off >>= 1) {
            o0 += __shfl_down_sync(0xffffffffu, o0, off);
            o1 += __shfl_down_sync(0xffffffffu, o1, off);
            o2 += __shfl_down_sync(0xffffffffu, o2, off);
        }
        if (j == 0) {
            out[g * 3 + 0] = o0 + b2[0];
            out[g * 3 + 1] = o1 + b2[1];
            out[g * 3 + 2] = o2 + b2[2];
        }
    }
}

// ======== launcher =======================================================
extern "C" void kernel_launch(void* const* d_in, const int* in_sizes, int n_in,
                              void* d_out, int out_size) {
    const float* x      = (const float*)d_in[0];
    const int*   ei     = (const int*)d_in[1];
    const int*   batch  = (const int*)d_in[2];
    const float* gin_w1 = (const float*)d_in[3];
    const float* gin_b1 = (const float*)d_in[4];
    const float* gin_w2 = (const float*)d_in[5];
    const float* gin_b2 = (const float*)d_in[6];
    const float* gcn_w  = (const float*)d_in[7];
    const float* gcn_b  = (const float*)d_in[8];
    const float* lin1_w = (const float*)d_in[9];
    const float* lin1_b = (const float*)d_in[10];
    const float* lin2_w = (const float*)d_in[11];
    const float* lin2_b = (const float*)d_in[12];
    float*       out    = (float*)d_out;

    const int N = in_sizes[0] / DIM;       // 100000
    const int E = in_sizes[1] / 2;         // 1600000

    __half* hx_p;   cudaGetSymbolAddress((void**)&hx_p,   g_hx);
    __half* agg_p;  cudaGetSymbolAddress((void**)&agg_p,  g_agg);
    __half* hh_p;   cudaGetSymbolAddress((void**)&hh_p,   g_hh);
    __half* t_p;    cudaGetSymbolAddress((void**)&t_p,    g_t);
    __half* wt_p;   cudaGetSymbolAddress((void**)&wt_p,   g_wt);
    float*  pool_p; cudaGetSymbolAddress((void**)&pool_p, g_pool);
    int*    cnt_p;  cudaGetSymbolAddress((void**)&cnt_p,  g_cnt);

    static bool attr_done = false;
    if (!attr_done) {
        cudaFuncSetAttribute(k_gin_mlp,   cudaFuncAttributeMaxDynamicSharedMemorySize, HS_TOT);
        cudaFuncSetAttribute(k_gemm_pool, cudaFuncAttributeMaxDynamicSharedMemorySize, HS_TOT);
        attr_done = true;
    }

    const int TB = 256;

    // CSR build + one-shot conversions
    cudaMemsetAsync(cnt_p, 0, N_NODES * sizeof(int));
    k_count<<<(E + TB - 1) / TB, TB>>>(ei, E);
    k_half<<<(N_NODES * (DIM / 4) + TB - 1) / TB, TB>>>(x);
    k_wconv<<<(3 * DIM * DIM + TB - 1) / TB, TB>>>(gin_w1, gin_w2, gcn_w);
    k_scanA<<<NSCAN, SCAN_B>>>();
    k_scanC<<<(N + TB - 1) / TB, TB>>>();
    k_fill<<<(E + TB - 1) / TB, TB>>>(ei, E);

    int pblocks = (N * 32 + TB - 1) / TB;
    // GIN aggregate (pull over fp16 x): agg = half(x + sum x[src])
    k_pull_h<0><<<pblocks, TB>>>(hx_p, agg_p);

    int gblocks = (N + 127) / 128;          // 782
    // hh = half(dinv * relu(relu(agg@W1+b1)@W2+b2))
    k_gin_mlp<<<gblocks, 256, HS_TOT>>>(agg_p, wt_p + 0 * DIM * DIM, gin_b1,
                                        wt_p + 1 * DIM * DIM, gin_b2, hh_p, N);

    cudaMemsetAsync(pool_p, 0, N_GRAPHS * DIM * sizeof(float));

    // GCN aggregate (pull over fp16 h): t = half(dinv * (h + sum h[src]))
    k_pull_h<1><<<pblocks, TB>>>(hh_p, t_p);

    // pool[batch] += relu(t @ gcn_w + gcn_b)
    k_gemm_pool<<<gblocks, 256, HS_TOT>>>(t_p, wt_p + 2 * DIM * DIM, gcn_b,
                                          batch, pool_p, N);

    k_head<<<N_GRAPHS, 128>>>(lin1_w, lin1_b, lin2_w, lin2_b, out);
}